// round 8
// baseline (speedup 1.0000x reference)
#include <cuda_runtime.h>
#include <cstdint>

#define NB 4
#define NS 8192
#define ND 512
#define NP 32
#define NT (NP + NS)          // 8224
#define LN_EPS 1e-5f
#define ZCH 128               // chunks over S for reduce (R4-proven)
#define CROWS (NS / ZCH)      // 64 rows per chunk
#define KZ 8                  // split-K factor for GEMVs
#define KS (ND / KZ)          // 64 k per split

// Scratch: device globals, referenced ONLY from device code.
__device__ float g_part[ZCH][NB * ND];   // per-chunk partial sums of x
__device__ float g_vp[KZ][NB * ND];      // split-K partials of vbar
__device__ float g_yp[KZ][NB * ND];      // split-K partials of y

__device__ __forceinline__ uint32_t smem_u32(const void* p) {
    uint32_t a;
    asm("{ .reg .u64 t; cvta.to.shared.u64 t, %1; cvt.u32.u64 %0, t; }"
        : "=r"(a) : "l"(p));
    return a;
}

// ---------------------------------------------------------------------------
// K1: reduce x over S. grid (NB, ZCH), block 128. float4 loads, 64 rows/thr,
// 8 independent accumulators. At the DRAM wall (read + prev-output writeback).
// ---------------------------------------------------------------------------
__global__ void reduce_x_kernel(const float4* __restrict__ x4) {
    const int d4 = threadIdx.x;            // 0..127
    const int b  = blockIdx.x;
    const int z  = blockIdx.y;
    const float4* p = x4 + ((size_t)(b * NS + z * CROWS)) * (ND / 4) + d4;
    float4 a[8];
#pragma unroll
    for (int j = 0; j < 8; j++) a[j] = make_float4(0.f, 0.f, 0.f, 0.f);
#pragma unroll
    for (int i = 0; i < CROWS; i += 8) {
#pragma unroll
        for (int j = 0; j < 8; j++) {
            float4 v = p[(size_t)(i + j) * (ND / 4)];
            a[j].x += v.x; a[j].y += v.y; a[j].z += v.z; a[j].w += v.w;
        }
    }
    float4 r;
    r.x = ((a[0].x + a[1].x) + (a[2].x + a[3].x)) + ((a[4].x + a[5].x) + (a[6].x + a[7].x));
    r.y = ((a[0].y + a[1].y) + (a[2].y + a[3].y)) + ((a[4].y + a[5].y) + (a[6].y + a[7].y));
    r.z = ((a[0].z + a[1].z) + (a[2].z + a[3].z)) + ((a[4].z + a[5].z) + (a[6].z + a[7].z));
    r.w = ((a[0].w + a[1].w) + (a[2].w + a[3].w)) + ((a[4].w + a[5].w) + (a[6].w + a[7].w));
    ((float4*)g_part[z])[b * (ND / 4) + d4] = r;
}

// ---------------------------------------------------------------------------
// K2: fused cbar + split-K GEMV1 (vbar partials). grid (NB, KZ), block 512.
// ---------------------------------------------------------------------------
__global__ void gemv1_kernel(const float* __restrict__ pm,
                             const float* __restrict__ Wv) {
    const int b = blockIdx.x, z = blockIdx.y, d = threadIdx.x;
    __shared__ float sk[KS];
    if (d < KS) {
        const int kk = z * KS + d;
        float a = 0.f;
#pragma unroll 16
        for (int c = 0; c < ZCH; c++) a += g_part[c][b * ND + kk];
#pragma unroll
        for (int p = 0; p < NP; p++) a += pm[p * ND + kk];
        sk[d] = a / (float)NT;
    }
    __syncthreads();
    const float* w = Wv + (size_t)(z * KS) * ND + d;
    float acc = 0.f;
#pragma unroll
    for (int k = 0; k < KS; k++) acc += sk[k] * w[(size_t)k * ND];
    g_vp[z][b * ND + d] = acc;
}

// ---------------------------------------------------------------------------
// K3: fused vbar-combine + LayerNorm + split-K GEMV2 (y partials).
// grid (NB, KZ), block 512.
// ---------------------------------------------------------------------------
__global__ void gemv2_kernel(const float* __restrict__ bv,
                             const float* __restrict__ gamma,
                             const float* __restrict__ beta,
                             const float* __restrict__ Wout) {
    const int b = blockIdx.x, z = blockIdx.y, d = threadIdx.x;
    __shared__ float red[ND];
    __shared__ float snorm[KS];

    float vb = bv[d];
#pragma unroll
    for (int c = 0; c < KZ; c++) vb += g_vp[c][b * ND + d];

    red[d] = vb;
    __syncthreads();
    for (int s = ND / 2; s > 0; s >>= 1) {
        if (d < s) red[d] += red[d + s];
        __syncthreads();
    }
    const float mu = red[0] / (float)ND;
    __syncthreads();
    const float diff = vb - mu;
    red[d] = diff * diff;
    __syncthreads();
    for (int s = ND / 2; s > 0; s >>= 1) {
        if (d < s) red[d] += red[d + s];
        __syncthreads();
    }
    const float inv = rsqrtf(red[0] / (float)ND + LN_EPS);
    const float nrm = diff * inv * gamma[d] + beta[d];
    if (d >= z * KS && d < (z + 1) * KS) snorm[d - z * KS] = nrm;
    __syncthreads();

    const float* w = Wout + (size_t)(z * KS) * ND + d;
    float acc = 0.f;
#pragma unroll
    for (int k = 0; k < KS; k++) acc += snorm[k] * w[(size_t)k * ND];
    g_yp[z][b * ND + d] = acc;
}

// ---------------------------------------------------------------------------
// K4: combine y partials + bout, broadcast via TMA bulk stores.
// grid (257, NB), block 128. Each block: replicate the 2KB row 16x in SMEM
// (32KB), then two 32KB cp.async.bulk copies to its contiguous 64KB chunk.
// Bypasses the per-lane STG path entirely.
// ---------------------------------------------------------------------------
#define BROWS 32
#define BGX (NT / BROWS)      // 257
#define REP 16                // rows replicated in SMEM (32KB)
__global__ void bcast_kernel(const float4* __restrict__ bout4,
                             float* __restrict__ out) {
    const int b = blockIdx.y;
    const int tid = threadIdx.x;   // 0..127
    __shared__ alignas(128) float4 srow[REP * (ND / 4)];  // 32KB

    {
        float4 a = bout4[tid];
#pragma unroll
        for (int z = 0; z < KZ; z++) {
            float4 v = ((const float4*)g_yp[z])[b * (ND / 4) + tid];
            a.x += v.x; a.y += v.y; a.z += v.z; a.w += v.w;
        }
#pragma unroll
        for (int r = 0; r < REP; r++) srow[r * (ND / 4) + tid] = a;
    }
    __syncthreads();
    asm volatile("fence.proxy.async.shared::cta;" ::: "memory");

    if (tid == 0) {
        const uint32_t saddr = smem_u32(srow);
        char* dst = (char*)out +
                    ((size_t)b * NT * ND + (size_t)blockIdx.x * BROWS * ND) * 4;
        asm volatile("cp.async.bulk.global.shared::cta.bulk_group [%0], [%1], %2;"
                     :: "l"(dst), "r"(saddr), "r"(REP * ND * 4) : "memory");
        asm volatile("cp.async.bulk.global.shared::cta.bulk_group [%0], [%1], %2;"
                     :: "l"(dst + REP * ND * 4), "r"(saddr), "r"(REP * ND * 4) : "memory");
        asm volatile("cp.async.bulk.commit_group;" ::: "memory");
        asm volatile("cp.async.bulk.wait_group 0;" ::: "memory");
    }
}

// ---------------------------------------------------------------------------
extern "C" void kernel_launch(void* const* d_in, const int* in_sizes, int n_in,
                              void* d_out, int out_size) {
    const float* x     = (const float*)d_in[0];
    const float* pm    = (const float*)d_in[1];
    // d_in[2]=Wk, [3]=bk, [6]=Wq, [7]=bq unused: softmax over zero-state and
    // constant-in-m logits collapse to uniform attention weights.
    const float* Wv    = (const float*)d_in[4];
    const float* bv    = (const float*)d_in[5];
    const float* gamma = (const float*)d_in[8];
    const float* beta  = (const float*)d_in[9];
    const float* Wout  = (const float*)d_in[10];
    const float* bout  = (const float*)d_in[11];

    reduce_x_kernel<<<dim3(NB, ZCH), 128>>>((const float4*)x);
    gemv1_kernel<<<dim3(NB, KZ), ND>>>(pm, Wv);
    gemv2_kernel<<<dim3(NB, KZ), ND>>>(bv, gamma, beta, Wout);
    bcast_kernel<<<dim3(BGX, NB), 128>>>((const float4*)bout, (float*)d_out);
}

// round 9
// speedup vs baseline: 1.0790x; 1.0790x over previous
#include <cuda_runtime.h>
#include <cooperative_groups.h>
#include <cstdint>

namespace cg = cooperative_groups;

#define NB 4
#define NS 8192
#define ND 512
#define NP 32
#define NT (NP + NS)          // 8224
#define LN_EPS 1e-5f
#define ZCH 128               // chunks over S for reduce (R4/R7-proven)
#define CROWS (NS / ZCH)      // 64 rows per chunk
#define KZ 8                  // split-K factor for GEMVs
#define KS (ND / KZ)          // 64 k per split

// Scratch: device globals, referenced ONLY from device code.
__device__ float g_part[ZCH][NB * ND];   // per-chunk partial sums of x
__device__ float g_vp[KZ][NB * ND];      // split-K partials of vbar
__device__ float g_yp[KZ][NB * ND];      // split-K partials of y

// ---------------------------------------------------------------------------
// K1: reduce x over S. grid (NB, ZCH), block 128. float4 loads, 64 rows/thr,
// 8 independent accumulators (proven 16.5us floor).
// ---------------------------------------------------------------------------
__global__ void reduce_x_kernel(const float4* __restrict__ x4) {
    const int d4 = threadIdx.x;            // 0..127
    const int b  = blockIdx.x;
    const int z  = blockIdx.y;
    const float4* p = x4 + ((size_t)(b * NS + z * CROWS)) * (ND / 4) + d4;
    float4 a[8];
#pragma unroll
    for (int j = 0; j < 8; j++) a[j] = make_float4(0.f, 0.f, 0.f, 0.f);
#pragma unroll
    for (int i = 0; i < CROWS; i += 8) {
#pragma unroll
        for (int j = 0; j < 8; j++) {
            float4 v = p[(size_t)(i + j) * (ND / 4)];
            a[j].x += v.x; a[j].y += v.y; a[j].z += v.z; a[j].w += v.w;
        }
    }
    float4 r;
    r.x = ((a[0].x + a[1].x) + (a[2].x + a[3].x)) + ((a[4].x + a[5].x) + (a[6].x + a[7].x));
    r.y = ((a[0].y + a[1].y) + (a[2].y + a[3].y)) + ((a[4].y + a[5].y) + (a[6].y + a[7].y));
    r.z = ((a[0].z + a[1].z) + (a[2].z + a[3].z)) + ((a[4].z + a[5].z) + (a[6].z + a[7].z));
    r.w = ((a[0].w + a[1].w) + (a[2].w + a[3].w)) + ((a[4].w + a[5].w) + (a[6].w + a[7].w));
    ((float4*)g_part[z])[b * (ND / 4) + d4] = r;
}

// ---------------------------------------------------------------------------
// K2: cooperative fused GEMV: cbar + GEMV1, grid.sync, LN + GEMV2.
// grid (NB, KZ) = 32 blocks, block 512. Phase bodies identical to the proven
// split kernels; only the kernel boundary is replaced by grid::sync().
// ---------------------------------------------------------------------------
__global__ void gemv_fused_kernel(const float* __restrict__ pm,
                                  const float* __restrict__ Wv,
                                  const float* __restrict__ bv,
                                  const float* __restrict__ gamma,
                                  const float* __restrict__ beta,
                                  const float* __restrict__ Wout) {
    cg::grid_group grid = cg::this_grid();
    const int b = blockIdx.x, z = blockIdx.y, d = threadIdx.x;
    __shared__ float sk[KS];
    __shared__ float red[ND];
    __shared__ float snorm[KS];

    // --- Phase A: cbar slice + GEMV1 partial ---
    if (d < KS) {
        const int kk = z * KS + d;
        float a = 0.f;
#pragma unroll 16
        for (int c = 0; c < ZCH; c++) a += g_part[c][b * ND + kk];
#pragma unroll
        for (int p = 0; p < NP; p++) a += pm[p * ND + kk];
        sk[d] = a / (float)NT;
    }
    __syncthreads();
    {
        const float* w = Wv + (size_t)(z * KS) * ND + d;
        float acc = 0.f;
#pragma unroll
        for (int k = 0; k < KS; k++) acc += sk[k] * w[(size_t)k * ND];
        g_vp[z][b * ND + d] = acc;
    }

    grid.sync();

    // --- Phase B: combine vbar + LayerNorm (redundant per block, fixed order) ---
    float vb = bv[d];
#pragma unroll
    for (int c = 0; c < KZ; c++) vb += g_vp[c][b * ND + d];

    red[d] = vb;
    __syncthreads();
    for (int s = ND / 2; s > 0; s >>= 1) {
        if (d < s) red[d] += red[d + s];
        __syncthreads();
    }
    const float mu = red[0] / (float)ND;
    __syncthreads();
    const float diff = vb - mu;
    red[d] = diff * diff;
    __syncthreads();
    for (int s = ND / 2; s > 0; s >>= 1) {
        if (d < s) red[d] += red[d + s];
        __syncthreads();
    }
    const float inv = rsqrtf(red[0] / (float)ND + LN_EPS);
    const float nrm = diff * inv * gamma[d] + beta[d];
    if (d >= z * KS && d < (z + 1) * KS) snorm[d - z * KS] = nrm;
    __syncthreads();

    // --- Phase C: GEMV2 partial ---
    const float* w = Wout + (size_t)(z * KS) * ND + d;
    float acc = 0.f;
#pragma unroll
    for (int k = 0; k < KS; k++) acc += snorm[k] * w[(size_t)k * ND];
    g_yp[z][b * ND + d] = acc;
}

// ---------------------------------------------------------------------------
// K3: combine y partials + bout, broadcast. grid (257, NB), block 256.
// R7-proven: contiguous 64KB chunk per block, loop-invariant value,
// streaming st.global.cs.
// ---------------------------------------------------------------------------
#define BROWS 32
#define BGX (NT / BROWS)      // 257
__global__ void bcast_kernel(const float4* __restrict__ bout4,
                             float* __restrict__ out) {
    const int b = blockIdx.y;
    const int tid = threadIdx.x;
    __shared__ float4 sy[ND / 4];
    if (tid < ND / 4) {
        float4 a = bout4[tid];
#pragma unroll
        for (int z = 0; z < KZ; z++) {
            float4 v = ((const float4*)g_yp[z])[b * (ND / 4) + tid];
            a.x += v.x; a.y += v.y; a.z += v.z; a.w += v.w;
        }
        sy[tid] = a;
    }
    __syncthreads();

    const size_t chunk0 = (size_t)blockIdx.x * (BROWS * (ND / 4));
    const float4 val = sy[(chunk0 + tid) & (ND / 4 - 1)];  // invariant per thread
    float4* o = (float4*)out + (size_t)b * NT * (ND / 4) + chunk0 + tid;
#pragma unroll
    for (int j = 0; j < BROWS * (ND / 4) / 256; j++) {     // 16 iterations
        asm volatile("st.global.cs.v4.f32 [%0], {%1, %2, %3, %4};"
                     :: "l"(o + (size_t)j * 256),
                        "f"(val.x), "f"(val.y), "f"(val.z), "f"(val.w)
                     : "memory");
    }
}

// ---------------------------------------------------------------------------
extern "C" void kernel_launch(void* const* d_in, const int* in_sizes, int n_in,
                              void* d_out, int out_size) {
    const float* x     = (const float*)d_in[0];
    const float* pm    = (const float*)d_in[1];
    // d_in[2]=Wk, [3]=bk, [6]=Wq, [7]=bq unused: softmax over zero-state and
    // constant-in-m logits collapse to uniform attention weights.
    const float* Wv    = (const float*)d_in[4];
    const float* bv    = (const float*)d_in[5];
    const float* gamma = (const float*)d_in[8];
    const float* beta  = (const float*)d_in[9];
    const float* Wout  = (const float*)d_in[10];
    const float* bout  = (const float*)d_in[11];

    reduce_x_kernel<<<dim3(NB, ZCH), 128>>>((const float4*)x);

    {
        void* args[] = { (void*)&pm, (void*)&Wv, (void*)&bv,
                         (void*)&gamma, (void*)&beta, (void*)&Wout };
        cudaLaunchCooperativeKernel((const void*)gemv_fused_kernel,
                                    dim3(NB, KZ), dim3(ND), args, 0, 0);
    }

    bcast_kernel<<<dim3(BGX, NB), 256>>>((const float4*)bout, (float*)d_out);
}

// round 10
// speedup vs baseline: 1.1381x; 1.0548x over previous
#include <cuda_runtime.h>
#include <cooperative_groups.h>
#include <cstdint>

namespace cg = cooperative_groups;

#define NB 4
#define NS 8192
#define ND 512
#define NP 32
#define NT (NP + NS)          // 8224
#define LN_EPS 1e-5f
#define ZCH 128               // chunks over S for reduce
#define CROWS (NS / ZCH)      // 64 rows per chunk
#define KZ 8                  // split-K factor for GEMVs
#define KS (ND / KZ)          // 64 k per split
#define NQ (ND / 4)           // 128 column-quads

// Scratch: device globals (float4 for aligned vector access), device-side only.
__device__ float4 g_part4[ZCH][NB * NQ];  // per-chunk partial sums of x
__device__ float4 g_vp4[KZ][NB * NQ];     // split-K partials of vbar
__device__ float4 g_yp4[KZ][NB * NQ];     // split-K partials of y

// ---------------------------------------------------------------------------
// K1: reduce x over S. grid (NB, ZCH), block 128. float4 loads, 64 rows/thr,
// 8 independent accumulators. At the DRAM wall (x read + prev-output wb).
// ---------------------------------------------------------------------------
__global__ void reduce_x_kernel(const float4* __restrict__ x4) {
    const int d4 = threadIdx.x;            // 0..127
    const int b  = blockIdx.x;
    const int z  = blockIdx.y;
    const float4* p = x4 + ((size_t)(b * NS + z * CROWS)) * NQ + d4;
    float4 a[8];
#pragma unroll
    for (int j = 0; j < 8; j++) a[j] = make_float4(0.f, 0.f, 0.f, 0.f);
#pragma unroll
    for (int i = 0; i < CROWS; i += 8) {
#pragma unroll
        for (int j = 0; j < 8; j++) {
            float4 v = p[(size_t)(i + j) * NQ];
            a[j].x += v.x; a[j].y += v.y; a[j].z += v.z; a[j].w += v.w;
        }
    }
    float4 r;
    r.x = ((a[0].x + a[1].x) + (a[2].x + a[3].x)) + ((a[4].x + a[5].x) + (a[6].x + a[7].x));
    r.y = ((a[0].y + a[1].y) + (a[2].y + a[3].y)) + ((a[4].y + a[5].y) + (a[6].y + a[7].y));
    r.z = ((a[0].z + a[1].z) + (a[2].z + a[3].z)) + ((a[4].z + a[5].z) + (a[6].z + a[7].z));
    r.w = ((a[0].w + a[1].w) + (a[2].w + a[3].w)) + ((a[4].w + a[5].w) + (a[6].w + a[7].w));
    g_part4[z][b * NQ + d4] = r;
}

// ---------------------------------------------------------------------------
// Warp-shuffle block sum over 512 threads (deterministic fixed order).
// Returns total to ALL threads. Uses 2 __syncthreads.
// ---------------------------------------------------------------------------
__device__ __forceinline__ float block_sum_512(float v, float* wred, float* bcastp) {
    const int t = threadIdx.x;
    const int lane = t & 31, wid = t >> 5;
#pragma unroll
    for (int off = 16; off > 0; off >>= 1)
        v += __shfl_xor_sync(0xffffffffu, v, off);
    if (lane == 0) wred[wid] = v;
    __syncthreads();
    if (wid == 0) {
        float s = (lane < 16) ? wred[lane] : 0.f;
#pragma unroll
        for (int off = 8; off > 0; off >>= 1)
            s += __shfl_xor_sync(0xffffffffu, s, off);
        if (lane == 0) *bcastp = s;
    }
    __syncthreads();
    return *bcastp;
}

// ---------------------------------------------------------------------------
// K2: cooperative fused middle. grid (NB, KZ) = 32 blocks, block 512.
//  A: cbar slice (8-way chunk-split) + GEMV1 partial (float4 weights, 4-way
//     k-split, 16-deep chains)  ->  g_vp4
//  grid.sync
//  B: vbar combine + shuffle-LN  ->  snorm slice
//  C: GEMV2 partial (same quad layout)  ->  g_yp4
// ---------------------------------------------------------------------------
__global__ void gemv_fused_kernel(const float* __restrict__ pm,
                                  const float4* __restrict__ Wv4,
                                  const float* __restrict__ bv,
                                  const float* __restrict__ gamma,
                                  const float* __restrict__ beta,
                                  const float4* __restrict__ Wout4) {
    cg::grid_group grid = cg::this_grid();
    const int b = blockIdx.x, z = blockIdx.y, t = threadIdx.x;
    __shared__ float  spart[8][KS];    // cbar chunk-group partials
    __shared__ float  sk[KS];          // cbar slice for this split
    __shared__ float4 sacc[4][NQ];     // GEMV k-split partials (8KB)
    __shared__ float  ssn[KS];         // snorm slice
    __shared__ float  wred[16], sbc[2];

    // --- Phase A1: cbar slice, 8 chunk-groups x 64 k ---
    {
        const int kl = t & 63, g = t >> 6;         // g in 0..7
        const int k  = z * KS + kl;
        const float* gp = (const float*)g_part4[0] + b * ND + k;
        float a = 0.f;
#pragma unroll
        for (int c = 0; c < ZCH / 8; c++)          // 16 chunks per group
            a += gp[(size_t)(g * (ZCH / 8) + c) * (NB * ND)];
#pragma unroll
        for (int p = 0; p < NP / 8; p++)           // 4 pm rows per group
            a += pm[(g * (NP / 8) + p) * ND + k];
        spart[g][kl] = a;
    }
    __syncthreads();
    if (t < KS) {
        float a = 0.f;
#pragma unroll
        for (int g = 0; g < 8; g++) a += spart[g][t];
        sk[t] = a / (float)NT;
    }
    __syncthreads();

    // --- Phase A2: GEMV1 partial, quad outputs, 4-way k-split ---
    {
        const int q = t & 127, s = t >> 7;         // s in 0..3
        const int k0 = z * KS + s * 16;
        float4 acc = make_float4(0.f, 0.f, 0.f, 0.f);
#pragma unroll
        for (int j = 0; j < 16; j++) {
            float4 w = Wv4[(size_t)(k0 + j) * NQ + q];
            float  c = sk[s * 16 + j];
            acc.x += c * w.x; acc.y += c * w.y; acc.z += c * w.z; acc.w += c * w.w;
        }
        sacc[s][q] = acc;
    }
    __syncthreads();
    if (t < NQ) {
        float4 r = sacc[0][t];
        float4 a1 = sacc[1][t], a2 = sacc[2][t], a3 = sacc[3][t];
        r.x = (r.x + a1.x) + (a2.x + a3.x);
        r.y = (r.y + a1.y) + (a2.y + a3.y);
        r.z = (r.z + a1.z) + (a2.z + a3.z);
        r.w = (r.w + a1.w) + (a2.w + a3.w);
        g_vp4[z][b * NQ + t] = r;
    }

    grid.sync();

    // --- Phase B: vbar combine + shuffle LayerNorm ---
    const int d = t;
    float vb = bv[d];
#pragma unroll
    for (int c = 0; c < KZ; c++)
        vb += ((const float*)g_vp4[c])[b * ND + d];

    const float mu = block_sum_512(vb, wred, &sbc[0]) / (float)ND;
    const float diff = vb - mu;
    const float var = block_sum_512(diff * diff, wred, &sbc[1]) / (float)ND;
    const float inv = rsqrtf(var + LN_EPS);
    const float nrm = diff * inv * gamma[d] + beta[d];
    __syncthreads();
    if ((d >> 6) == z) ssn[d & 63] = nrm;
    __syncthreads();

    // --- Phase C: GEMV2 partial, same quad layout ---
    {
        const int q = t & 127, s = t >> 7;
        const int k0 = z * KS + s * 16;
        float4 acc = make_float4(0.f, 0.f, 0.f, 0.f);
#pragma unroll
        for (int j = 0; j < 16; j++) {
            float4 w = Wout4[(size_t)(k0 + j) * NQ + q];
            float  c = ssn[s * 16 + j];
            acc.x += c * w.x; acc.y += c * w.y; acc.z += c * w.z; acc.w += c * w.w;
        }
        sacc[s][q] = acc;
    }
    __syncthreads();
    if (t < NQ) {
        float4 r = sacc[0][t];
        float4 a1 = sacc[1][t], a2 = sacc[2][t], a3 = sacc[3][t];
        r.x = (r.x + a1.x) + (a2.x + a3.x);
        r.y = (r.y + a1.y) + (a2.y + a3.y);
        r.z = (r.z + a1.z) + (a2.z + a3.z);
        r.w = (r.w + a1.w) + (a2.w + a3.w);
        g_yp4[z][b * NQ + t] = r;
    }
}

// ---------------------------------------------------------------------------
// K3: combine y partials + bout, broadcast. grid (257, NB), block 256.
// R7-proven: contiguous 64KB chunk per block, loop-invariant value, st.cs.
// ---------------------------------------------------------------------------
#define BROWS 32
#define BGX (NT / BROWS)      // 257
__global__ void bcast_kernel(const float4* __restrict__ bout4,
                             float* __restrict__ out) {
    const int b = blockIdx.y;
    const int tid = threadIdx.x;
    __shared__ float4 sy[NQ];
    if (tid < NQ) {
        float4 a = bout4[tid];
#pragma unroll
        for (int z = 0; z < KZ; z++) {
            float4 v = g_yp4[z][b * NQ + tid];
            a.x += v.x; a.y += v.y; a.z += v.z; a.w += v.w;
        }
        sy[tid] = a;
    }
    __syncthreads();

    const size_t chunk0 = (size_t)blockIdx.x * (BROWS * NQ);
    const float4 val = sy[(chunk0 + tid) & (NQ - 1)];  // invariant per thread
    float4* o = (float4*)out + (size_t)b * NT * NQ + chunk0 + tid;
#pragma unroll
    for (int j = 0; j < BROWS * NQ / 256; j++) {       // 16 iterations
        asm volatile("st.global.cs.v4.f32 [%0], {%1, %2, %3, %4};"
                     :: "l"(o + (size_t)j * 256),
                        "f"(val.x), "f"(val.y), "f"(val.z), "f"(val.w)
                     : "memory");
    }
}

// ---------------------------------------------------------------------------
extern "C" void kernel_launch(void* const* d_in, const int* in_sizes, int n_in,
                              void* d_out, int out_size) {
    const float* x     = (const float*)d_in[0];
    const float* pm    = (const float*)d_in[1];
    // d_in[2]=Wk, [3]=bk, [6]=Wq, [7]=bq unused: softmax over zero-state and
    // constant-in-m logits collapse to uniform attention weights.
    const float* Wv    = (const float*)d_in[4];
    const float* bv    = (const float*)d_in[5];
    const float* gamma = (const float*)d_in[8];
    const float* beta  = (const float*)d_in[9];
    const float* Wout  = (const float*)d_in[10];
    const float* bout  = (const float*)d_in[11];

    reduce_x_kernel<<<dim3(NB, ZCH), 128>>>((const float4*)x);

    {
        const float4* Wv4 = (const float4*)Wv;
        const float4* Wout4 = (const float4*)Wout;
        void* args[] = { (void*)&pm, (void*)&Wv4, (void*)&bv,
                         (void*)&gamma, (void*)&beta, (void*)&Wout4 };
        cudaLaunchCooperativeKernel((const void*)gemv_fused_kernel,
                                    dim3(NB, KZ), dim3(ND), args, 0, 0);
    }

    bcast_kernel<<<dim3(BGX, NB), 256>>>((const float4*)bout, (float*)d_out);
}

// round 11
// speedup vs baseline: 1.2553x; 1.1030x over previous
#include <cuda_runtime.h>
#include <cooperative_groups.h>
#include <cstdint>

namespace cg = cooperative_groups;

#define NB 4
#define NS 8192
#define ND 512
#define NP 32
#define NT (NP + NS)          // 8224
#define LN_EPS 1e-5f
#define ZCH 128               // chunks over S for reduce
#define CROWS (NS / ZCH)      // 64 rows per chunk
#define KZ 8                  // split-K factor for GEMVs
#define KS (ND / KZ)          // 64 k per split
#define NQ (ND / 4)           // 128 column-quads

// Scratch: device globals (float4 for aligned vector access), device-side only.
__device__ float4 g_part4[ZCH][NB * NQ];  // per-chunk partial sums of x
__device__ float4 g_vp4[KZ][NB * NQ];     // split-K partials of vbar
__device__ float4 g_yp4[KZ][NB * NQ];     // split-K partials of y

// ---------------------------------------------------------------------------
// K1: reduce x over S. grid (NB, ZCH), block 128, 64 rows/thread.
// R11: __launch_bounds__(128,4) grants ~128 regs/thread; 16 float4 loads are
// explicitly staged in registers (MLP 16) before accumulating into 4 accums.
// Previous build had regs=43 -> MLP~2 -> latency-bound at 4.4 TB/s.
// ---------------------------------------------------------------------------
__global__ void __launch_bounds__(128, 4)
reduce_x_kernel(const float4* __restrict__ x4) {
    const int d4 = threadIdx.x;            // 0..127
    const int b  = blockIdx.x;
    const int z  = blockIdx.y;
    const float4* p = x4 + ((size_t)(b * NS + z * CROWS)) * NQ + d4;

    float4 a[4];
#pragma unroll
    for (int j = 0; j < 4; j++) a[j] = make_float4(0.f, 0.f, 0.f, 0.f);

#pragma unroll
    for (int i = 0; i < CROWS; i += 16) {
        float4 v[16];
#pragma unroll
        for (int j = 0; j < 16; j++)
            v[j] = p[(size_t)(i + j) * NQ];
#pragma unroll
        for (int j = 0; j < 16; j++) {
            a[j & 3].x += v[j].x;
            a[j & 3].y += v[j].y;
            a[j & 3].z += v[j].z;
            a[j & 3].w += v[j].w;
        }
    }
    float4 r;
    r.x = (a[0].x + a[1].x) + (a[2].x + a[3].x);
    r.y = (a[0].y + a[1].y) + (a[2].y + a[3].y);
    r.z = (a[0].z + a[1].z) + (a[2].z + a[3].z);
    r.w = (a[0].w + a[1].w) + (a[2].w + a[3].w);
    g_part4[z][b * NQ + d4] = r;
}

// ---------------------------------------------------------------------------
// Warp-shuffle block sum over 512 threads (deterministic fixed order).
// ---------------------------------------------------------------------------
__device__ __forceinline__ float block_sum_512(float v, float* wred, float* bcastp) {
    const int t = threadIdx.x;
    const int lane = t & 31, wid = t >> 5;
#pragma unroll
    for (int off = 16; off > 0; off >>= 1)
        v += __shfl_xor_sync(0xffffffffu, v, off);
    if (lane == 0) wred[wid] = v;
    __syncthreads();
    if (wid == 0) {
        float s = (lane < 16) ? wred[lane] : 0.f;
#pragma unroll
        for (int off = 8; off > 0; off >>= 1)
            s += __shfl_xor_sync(0xffffffffu, s, off);
        if (lane == 0) *bcastp = s;
    }
    __syncthreads();
    return *bcastp;
}

// ---------------------------------------------------------------------------
// K2: cooperative fused middle (R10-proven). grid (NB, KZ)=32 blocks, 512 thr.
// ---------------------------------------------------------------------------
__global__ void gemv_fused_kernel(const float* __restrict__ pm,
                                  const float4* __restrict__ Wv4,
                                  const float* __restrict__ bv,
                                  const float* __restrict__ gamma,
                                  const float* __restrict__ beta,
                                  const float4* __restrict__ Wout4) {
    cg::grid_group grid = cg::this_grid();
    const int b = blockIdx.x, z = blockIdx.y, t = threadIdx.x;
    __shared__ float  spart[8][KS];
    __shared__ float  sk[KS];
    __shared__ float4 sacc[4][NQ];
    __shared__ float  ssn[KS];
    __shared__ float  wred[16], sbc[2];

    // --- Phase A1: cbar slice, 8 chunk-groups x 64 k ---
    {
        const int kl = t & 63, g = t >> 6;
        const int k  = z * KS + kl;
        const float* gp = (const float*)g_part4[0] + b * ND + k;
        float a = 0.f;
#pragma unroll
        for (int c = 0; c < ZCH / 8; c++)
            a += gp[(size_t)(g * (ZCH / 8) + c) * (NB * ND)];
#pragma unroll
        for (int p = 0; p < NP / 8; p++)
            a += pm[(g * (NP / 8) + p) * ND + k];
        spart[g][kl] = a;
    }
    __syncthreads();
    if (t < KS) {
        float a = 0.f;
#pragma unroll
        for (int g = 0; g < 8; g++) a += spart[g][t];
        sk[t] = a / (float)NT;
    }
    __syncthreads();

    // --- Phase A2: GEMV1 partial, quad outputs, 4-way k-split ---
    {
        const int q = t & 127, s = t >> 7;
        const int k0 = z * KS + s * 16;
        float4 acc = make_float4(0.f, 0.f, 0.f, 0.f);
#pragma unroll
        for (int j = 0; j < 16; j++) {
            float4 w = Wv4[(size_t)(k0 + j) * NQ + q];
            float  c = sk[s * 16 + j];
            acc.x += c * w.x; acc.y += c * w.y; acc.z += c * w.z; acc.w += c * w.w;
        }
        sacc[s][q] = acc;
    }
    __syncthreads();
    if (t < NQ) {
        float4 r = sacc[0][t];
        float4 a1 = sacc[1][t], a2 = sacc[2][t], a3 = sacc[3][t];
        r.x = (r.x + a1.x) + (a2.x + a3.x);
        r.y = (r.y + a1.y) + (a2.y + a3.y);
        r.z = (r.z + a1.z) + (a2.z + a3.z);
        r.w = (r.w + a1.w) + (a2.w + a3.w);
        g_vp4[z][b * NQ + t] = r;
    }

    grid.sync();

    // --- Phase B: vbar combine + shuffle LayerNorm ---
    const int d = t;
    float vb = bv[d];
#pragma unroll
    for (int c = 0; c < KZ; c++)
        vb += ((const float*)g_vp4[c])[b * ND + d];

    const float mu = block_sum_512(vb, wred, &sbc[0]) / (float)ND;
    const float diff = vb - mu;
    const float var = block_sum_512(diff * diff, wred, &sbc[1]) / (float)ND;
    const float inv = rsqrtf(var + LN_EPS);
    const float nrm = diff * inv * gamma[d] + beta[d];
    __syncthreads();
    if ((d >> 6) == z) ssn[d & 63] = nrm;
    __syncthreads();

    // --- Phase C: GEMV2 partial, same quad layout ---
    {
        const int q = t & 127, s = t >> 7;
        const int k0 = z * KS + s * 16;
        float4 acc = make_float4(0.f, 0.f, 0.f, 0.f);
#pragma unroll
        for (int j = 0; j < 16; j++) {
            float4 w = Wout4[(size_t)(k0 + j) * NQ + q];
            float  c = ssn[s * 16 + j];
            acc.x += c * w.x; acc.y += c * w.y; acc.z += c * w.z; acc.w += c * w.w;
        }
        sacc[s][q] = acc;
    }
    __syncthreads();
    if (t < NQ) {
        float4 r = sacc[0][t];
        float4 a1 = sacc[1][t], a2 = sacc[2][t], a3 = sacc[3][t];
        r.x = (r.x + a1.x) + (a2.x + a3.x);
        r.y = (r.y + a1.y) + (a2.y + a3.y);
        r.z = (r.z + a1.z) + (a2.z + a3.z);
        r.w = (r.w + a1.w) + (a2.w + a3.w);
        g_yp4[z][b * NQ + t] = r;
    }
}

// ---------------------------------------------------------------------------
// K3: combine y partials + bout, broadcast. grid (257, NB), block 256.
// R7-proven: contiguous 64KB chunk per block, loop-invariant value, st.cs.
// ---------------------------------------------------------------------------
#define BROWS 32
#define BGX (NT / BROWS)      // 257
__global__ void bcast_kernel(const float4* __restrict__ bout4,
                             float* __restrict__ out) {
    const int b = blockIdx.y;
    const int tid = threadIdx.x;
    __shared__ float4 sy[NQ];
    if (tid < NQ) {
        float4 a = bout4[tid];
#pragma unroll
        for (int z = 0; z < KZ; z++) {
            float4 v = g_yp4[z][b * NQ + tid];
            a.x += v.x; a.y += v.y; a.z += v.z; a.w += v.w;
        }
        sy[tid] = a;
    }
    __syncthreads();

    const size_t chunk0 = (size_t)blockIdx.x * (BROWS * NQ);
    const float4 val = sy[(chunk0 + tid) & (NQ - 1)];  // invariant per thread
    float4* o = (float4*)out + (size_t)b * NT * NQ + chunk0 + tid;
#pragma unroll
    for (int j = 0; j < BROWS * NQ / 256; j++) {       // 16 iterations
        asm volatile("st.global.cs.v4.f32 [%0], {%1, %2, %3, %4};"
                     :: "l"(o + (size_t)j * 256),
                        "f"(val.x), "f"(val.y), "f"(val.z), "f"(val.w)
                     : "memory");
    }
}

// ---------------------------------------------------------------------------
extern "C" void kernel_launch(void* const* d_in, const int* in_sizes, int n_in,
                              void* d_out, int out_size) {
    const float* x     = (const float*)d_in[0];
    const float* pm    = (const float*)d_in[1];
    // d_in[2]=Wk, [3]=bk, [6]=Wq, [7]=bq unused: softmax over zero-state and
    // constant-in-m logits collapse to uniform attention weights.
    const float* Wv    = (const float*)d_in[4];
    const float* bv    = (const float*)d_in[5];
    const float* gamma = (const float*)d_in[8];
    const float* beta  = (const float*)d_in[9];
    const float* Wout  = (const float*)d_in[10];
    const float* bout  = (const float*)d_in[11];

    reduce_x_kernel<<<dim3(NB, ZCH), 128>>>((const float4*)x);

    {
        const float4* Wv4 = (const float4*)Wv;
        const float4* Wout4 = (const float4*)Wout;
        void* args[] = { (void*)&pm, (void*)&Wv4, (void*)&bv,
                         (void*)&gamma, (void*)&beta, (void*)&Wout4 };
        cudaLaunchCooperativeKernel((const void*)gemv_fused_kernel,
                                    dim3(NB, KZ), dim3(ND), args, 0, 0);
    }

    bcast_kernel<<<dim3(BGX, NB), 256>>>((const float4*)bout, (float*)d_out);
}

// round 12
// speedup vs baseline: 1.3336x; 1.0624x over previous
#include <cuda_runtime.h>
#include <cooperative_groups.h>
#include <cstdint>

namespace cg = cooperative_groups;

#define NB 4
#define NS 8192
#define ND 512
#define NP 32
#define NT (NP + NS)          // 8224
#define LN_EPS 1e-5f
#define ZCH 128               // chunks over S for reduce
#define CROWS (NS / ZCH)      // 64 rows per chunk
#define KZ 8                  // split-K factor for GEMVs
#define KS (ND / KZ)          // 64 k per split
#define NQ (ND / 4)           // 128 column-quads
#define RGX 148               // reduce grid: exactly one wave

// Scratch: device globals (float4 for aligned vector access), device-side only.
__device__ float4 g_part4[ZCH][NB * NQ];  // per-chunk partial sums of x
__device__ float4 g_vp4[KZ][NB * NQ];     // split-K partials of vbar
__device__ float4 g_yp4[KZ][NB * NQ];     // split-K partials of y

// ---------------------------------------------------------------------------
// K1: reduce x over S. ONE WAVE: grid 148, block 512 (oe = 1).
// Each 128-thread quarter handles one (b,z) chunk of 64 rows with 16-deep
// staged LDG.128 (MLP 16). oe*MLP_p1 = 16 -> cross-CTA L1tex-queue spread
// collapses to the ~1.10 floor (B300 spread law), vs oe=4 before.
// ---------------------------------------------------------------------------
__global__ void __launch_bounds__(512, 1)
reduce_x_kernel(const float4* __restrict__ x4) {
    const int d4 = threadIdx.x & 127;
    const int g  = threadIdx.x >> 7;            // quarter 0..3
    const int u  = g * RGX + blockIdx.x;        // interleaved unit id, 0..591
    if (u >= NB * ZCH) return;                  // 512 units used
    const int b = u >> 7;                       // u / ZCH
    const int z = u & (ZCH - 1);                // u % ZCH

    const float4* p = x4 + ((size_t)(b * NS + z * CROWS)) * NQ + d4;

    float4 a[4];
#pragma unroll
    for (int j = 0; j < 4; j++) a[j] = make_float4(0.f, 0.f, 0.f, 0.f);

#pragma unroll
    for (int i = 0; i < CROWS; i += 16) {
        float4 v[16];
#pragma unroll
        for (int j = 0; j < 16; j++)
            v[j] = p[(size_t)(i + j) * NQ];
#pragma unroll
        for (int j = 0; j < 16; j++) {
            a[j & 3].x += v[j].x;
            a[j & 3].y += v[j].y;
            a[j & 3].z += v[j].z;
            a[j & 3].w += v[j].w;
        }
    }
    float4 r;
    r.x = (a[0].x + a[1].x) + (a[2].x + a[3].x);
    r.y = (a[0].y + a[1].y) + (a[2].y + a[3].y);
    r.z = (a[0].z + a[1].z) + (a[2].z + a[3].z);
    r.w = (a[0].w + a[1].w) + (a[2].w + a[3].w);
    g_part4[z][b * NQ + d4] = r;
}

// ---------------------------------------------------------------------------
// Warp-shuffle block sum over 512 threads (deterministic fixed order).
// ---------------------------------------------------------------------------
__device__ __forceinline__ float block_sum_512(float v, float* wred, float* bcastp) {
    const int t = threadIdx.x;
    const int lane = t & 31, wid = t >> 5;
#pragma unroll
    for (int off = 16; off > 0; off >>= 1)
        v += __shfl_xor_sync(0xffffffffu, v, off);
    if (lane == 0) wred[wid] = v;
    __syncthreads();
    if (wid == 0) {
        float s = (lane < 16) ? wred[lane] : 0.f;
#pragma unroll
        for (int off = 8; off > 0; off >>= 1)
            s += __shfl_xor_sync(0xffffffffu, s, off);
        if (lane == 0) *bcastp = s;
    }
    __syncthreads();
    return *bcastp;
}

// ---------------------------------------------------------------------------
// K2: cooperative fused middle (R10-proven). grid (NB, KZ)=32 blocks, 512 thr.
// ---------------------------------------------------------------------------
__global__ void gemv_fused_kernel(const float* __restrict__ pm,
                                  const float4* __restrict__ Wv4,
                                  const float* __restrict__ bv,
                                  const float* __restrict__ gamma,
                                  const float* __restrict__ beta,
                                  const float4* __restrict__ Wout4) {
    cg::grid_group grid = cg::this_grid();
    const int b = blockIdx.x, z = blockIdx.y, t = threadIdx.x;
    __shared__ float  spart[8][KS];
    __shared__ float  sk[KS];
    __shared__ float4 sacc[4][NQ];
    __shared__ float  ssn[KS];
    __shared__ float  wred[16], sbc[2];

    // --- Phase A1: cbar slice, 8 chunk-groups x 64 k ---
    {
        const int kl = t & 63, g = t >> 6;
        const int k  = z * KS + kl;
        const float* gp = (const float*)g_part4[0] + b * ND + k;
        float a = 0.f;
#pragma unroll
        for (int c = 0; c < ZCH / 8; c++)
            a += gp[(size_t)(g * (ZCH / 8) + c) * (NB * ND)];
#pragma unroll
        for (int p = 0; p < NP / 8; p++)
            a += pm[(g * (NP / 8) + p) * ND + k];
        spart[g][kl] = a;
    }
    __syncthreads();
    if (t < KS) {
        float a = 0.f;
#pragma unroll
        for (int g = 0; g < 8; g++) a += spart[g][t];
        sk[t] = a / (float)NT;
    }
    __syncthreads();

    // --- Phase A2: GEMV1 partial, quad outputs, 4-way k-split ---
    {
        const int q = t & 127, s = t >> 7;
        const int k0 = z * KS + s * 16;
        float4 acc = make_float4(0.f, 0.f, 0.f, 0.f);
#pragma unroll
        for (int j = 0; j < 16; j++) {
            float4 w = Wv4[(size_t)(k0 + j) * NQ + q];
            float  c = sk[s * 16 + j];
            acc.x += c * w.x; acc.y += c * w.y; acc.z += c * w.z; acc.w += c * w.w;
        }
        sacc[s][q] = acc;
    }
    __syncthreads();
    if (t < NQ) {
        float4 r = sacc[0][t];
        float4 a1 = sacc[1][t], a2 = sacc[2][t], a3 = sacc[3][t];
        r.x = (r.x + a1.x) + (a2.x + a3.x);
        r.y = (r.y + a1.y) + (a2.y + a3.y);
        r.z = (r.z + a1.z) + (a2.z + a3.z);
        r.w = (r.w + a1.w) + (a2.w + a3.w);
        g_vp4[z][b * NQ + t] = r;
    }

    grid.sync();

    // --- Phase B: vbar combine + shuffle LayerNorm ---
    const int d = t;
    float vb = bv[d];
#pragma unroll
    for (int c = 0; c < KZ; c++)
        vb += ((const float*)g_vp4[c])[b * ND + d];

    const float mu = block_sum_512(vb, wred, &sbc[0]) / (float)ND;
    const float diff = vb - mu;
    const float var = block_sum_512(diff * diff, wred, &sbc[1]) / (float)ND;
    const float inv = rsqrtf(var + LN_EPS);
    const float nrm = diff * inv * gamma[d] + beta[d];
    __syncthreads();
    if ((d >> 6) == z) ssn[d & 63] = nrm;
    __syncthreads();

    // --- Phase C: GEMV2 partial, same quad layout ---
    {
        const int q = t & 127, s = t >> 7;
        const int k0 = z * KS + s * 16;
        float4 acc = make_float4(0.f, 0.f, 0.f, 0.f);
#pragma unroll
        for (int j = 0; j < 16; j++) {
            float4 w = Wout4[(size_t)(k0 + j) * NQ + q];
            float  c = ssn[s * 16 + j];
            acc.x += c * w.x; acc.y += c * w.y; acc.z += c * w.z; acc.w += c * w.w;
        }
        sacc[s][q] = acc;
    }
    __syncthreads();
    if (t < NQ) {
        float4 r = sacc[0][t];
        float4 a1 = sacc[1][t], a2 = sacc[2][t], a3 = sacc[3][t];
        r.x = (r.x + a1.x) + (a2.x + a3.x);
        r.y = (r.y + a1.y) + (a2.y + a3.y);
        r.z = (r.z + a1.z) + (a2.z + a3.z);
        r.w = (r.w + a1.w) + (a2.w + a3.w);
        g_yp4[z][b * NQ + t] = r;
    }
}

// ---------------------------------------------------------------------------
// K3: combine y partials + bout, broadcast. grid (257, NB), block 256.
// R7-proven: contiguous 64KB chunk per block, loop-invariant value, st.cs.
// ---------------------------------------------------------------------------
#define BROWS 32
#define BGX (NT / BROWS)      // 257
__global__ void bcast_kernel(const float4* __restrict__ bout4,
                             float* __restrict__ out) {
    const int b = blockIdx.y;
    const int tid = threadIdx.x;
    __shared__ float4 sy[NQ];
    if (tid < NQ) {
        float4 a = bout4[tid];
#pragma unroll
        for (int z = 0; z < KZ; z++) {
            float4 v = g_yp4[z][b * NQ + tid];
            a.x += v.x; a.y += v.y; a.z += v.z; a.w += v.w;
        }
        sy[tid] = a;
    }
    __syncthreads();

    const size_t chunk0 = (size_t)blockIdx.x * (BROWS * NQ);
    const float4 val = sy[(chunk0 + tid) & (NQ - 1)];  // invariant per thread
    float4* o = (float4*)out + (size_t)b * NT * NQ + chunk0 + tid;
#pragma unroll
    for (int j = 0; j < BROWS * NQ / 256; j++) {       // 16 iterations
        asm volatile("st.global.cs.v4.f32 [%0], {%1, %2, %3, %4};"
                     :: "l"(o + (size_t)j * 256),
                        "f"(val.x), "f"(val.y), "f"(val.z), "f"(val.w)
                     : "memory");
    }
}

// ---------------------------------------------------------------------------
extern "C" void kernel_launch(void* const* d_in, const int* in_sizes, int n_in,
                              void* d_out, int out_size) {
    const float* x     = (const float*)d_in[0];
    const float* pm    = (const float*)d_in[1];
    // d_in[2]=Wk, [3]=bk, [6]=Wq, [7]=bq unused: softmax over zero-state and
    // constant-in-m logits collapse to uniform attention weights.
    const float* Wv    = (const float*)d_in[4];
    const float* bv    = (const float*)d_in[5];
    const float* gamma = (const float*)d_in[8];
    const float* beta  = (const float*)d_in[9];
    const float* Wout  = (const float*)d_in[10];
    const float* bout  = (const float*)d_in[11];

    reduce_x_kernel<<<RGX, 512>>>((const float4*)x);

    {
        const float4* Wv4 = (const float4*)Wv;
        const float4* Wout4 = (const float4*)Wout;
        void* args[] = { (void*)&pm, (void*)&Wv4, (void*)&bv,
                         (void*)&gamma, (void*)&beta, (void*)&Wout4 };
        cudaLaunchCooperativeKernel((const void*)gemv_fused_kernel,
                                    dim3(NB, KZ), dim3(ND), args, 0, 0);
    }

    bcast_kernel<<<dim3(BGX, NB), 256>>>((const float4*)bout, (float*)d_out);
}